// round 1
// baseline (speedup 1.0000x reference)
#include <cuda_runtime.h>
#include <math.h>

#define BATCH 4
#define SEQ   2048
#define DIM   256
#define NH    8
#define HSZ   32
#define NTOK  (BATCH*SEQ)        /* 8192 */
#define NELEM (NTOK*DIM)         /* 2097152 */

// ---------------- scratch (allocation-free: __device__ globals) ----------------
__device__ float g_h[NELEM];
__device__ float g_t[NELEM];
__device__ float g_q[NELEM];
__device__ float g_k[NELEM];
__device__ float g_v[NELEM];
__device__ float g_attn[NELEM];
__device__ float g_res[NELEM];
__device__ float g_o1[NELEM];

// ---------------- helpers ----------------
__device__ __forceinline__ float gelu_f(float x) {
    // jax.nn.gelu default (approximate=True, tanh form)
    float x3 = x * x * x;
    return 0.5f * x * (1.f + tanhf(0.7978845608028654f * (x + 0.044715f * x3)));
}

// ---------------- LayerNorm (optionally fused residual add) ----------------
// grid = NTOK, block = 256 (one thread per feature)
__global__ void ln_kernel(const float* __restrict__ x, const float* __restrict__ add,
                          const float* __restrict__ gamma, const float* __restrict__ beta,
                          float* __restrict__ res_out, float* __restrict__ out)
{
    const int t = blockIdx.x;
    const int d = threadIdx.x;
    const int idx = t * DIM + d;
    float v = x[idx];
    if (add) v += add[idx];
    if (res_out) res_out[idx] = v;

    __shared__ float sh[8];
    const int lane = d & 31, w = d >> 5;

    float s = v;
    #pragma unroll
    for (int o = 16; o > 0; o >>= 1) s += __shfl_xor_sync(0xffffffffu, s, o);
    if (lane == 0) sh[w] = s;
    __syncthreads();
    float tot = 0.f;
    #pragma unroll
    for (int i = 0; i < 8; i++) tot += sh[i];
    const float mean = tot * (1.f / 256.f);
    const float dv = v - mean;

    float s2 = dv * dv;
    #pragma unroll
    for (int o = 16; o > 0; o >>= 1) s2 += __shfl_xor_sync(0xffffffffu, s2, o);
    __syncthreads();
    if (lane == 0) sh[w] = s2;
    __syncthreads();
    float tot2 = 0.f;
    #pragma unroll
    for (int i = 0; i < 8; i++) tot2 += sh[i];
    const float var = tot2 * (1.f / 256.f);

    out[idx] = dv * rsqrtf(var + 1e-6f) * gamma[d] + beta[d];
}

// ---------------- GEMM: C[M,256] = A' @ B + bias (+epilogue) ----------------
// CONV=true: A' row t, col kk in [0,768): value = A[t*256 + kk - 256] with zero pad
//            at sequence edges (im2col of kernel-3 SAME conv, gathered on the fly;
//            the 3 taps are CONTIGUOUS token rows so loads stay coalesced).
// EPI: 0=none, 1=gelu, 2=+resid
// grid = (N/64=4, M/64=128), block = 256, BM=BN=64, BK=16, 4x4 per thread.
template<bool CONV, int EPI>
__global__ void gemm_kernel(const float* __restrict__ A, const float* __restrict__ Bm,
                            const float* __restrict__ bias, const float* __restrict__ resid,
                            float* __restrict__ C, int Kdim)
{
    __shared__ float As[16][64];   // transposed: As[k][m]
    __shared__ float Bs[16][64];

    const int tid  = threadIdx.x;
    const int tx   = tid & 15, ty = tid >> 4;
    const int row0 = blockIdx.y * 64;
    const int col0 = blockIdx.x * 64;
    const int aRow = tid >> 2;
    const int aCol = (tid & 3) << 2;
    const int bRow = tid >> 4;
    const int bCol = (tid & 15) << 2;

    float acc[4][4];
    #pragma unroll
    for (int i = 0; i < 4; i++)
        #pragma unroll
        for (int j = 0; j < 4; j++) acc[i][j] = 0.f;

    const int m = row0 + aRow;
    const int s = m & (SEQ - 1);

    for (int kk0 = 0; kk0 < Kdim; kk0 += 16) {
        #pragma unroll
        for (int u = 0; u < 4; u++) {
            const int kk = kk0 + aCol + u;
            float val;
            if (CONV) {
                const int ks = kk >> 8;  // tap index 0..2
                val = ((unsigned)(s + ks - 1) < (unsigned)SEQ) ? A[m * DIM + kk - DIM] : 0.f;
            } else {
                val = A[m * Kdim + kk];
            }
            As[aCol + u][aRow] = val;
        }
        const float4 bv = *(const float4*)&Bm[(kk0 + bRow) * DIM + col0 + bCol];
        *(float4*)&Bs[bRow][bCol] = bv;
        __syncthreads();

        #pragma unroll
        for (int k = 0; k < 16; k++) {
            float a[4];
            #pragma unroll
            for (int i = 0; i < 4; i++) a[i] = As[k][ty * 4 + i];
            const float4 b4 = *(const float4*)&Bs[k][tx * 4];
            const float b[4] = {b4.x, b4.y, b4.z, b4.w};
            #pragma unroll
            for (int i = 0; i < 4; i++)
                #pragma unroll
                for (int j = 0; j < 4; j++) acc[i][j] = fmaf(a[i], b[j], acc[i][j]);
        }
        __syncthreads();
    }

    #pragma unroll
    for (int i = 0; i < 4; i++) {
        const int row = row0 + ty * 4 + i;
        #pragma unroll
        for (int j = 0; j < 4; j++) {
            const int col = col0 + tx * 4 + j;
            float c = acc[i][j] + bias[col];
            if (EPI == 1) c = gelu_f(c);
            if (EPI == 2) c += resid[row * DIM + col];
            C[row * DIM + col] = c;
        }
    }
}

// ---------------- Flash attention ----------------
// grid = (SEQ/8, NH, BATCH), block = 256 (8 warps, warp = one query row).
// Online softmax, 32-key smem tiles shared by the 8 warps. Lane j scores key j;
// lane d accumulates output dim d. Mask: additive -1e30 (matches reference).
__global__ void attn_kernel(const float* __restrict__ q, const float* __restrict__ k,
                            const float* __restrict__ v, const int* __restrict__ mask,
                            float* __restrict__ out)
{
    const int lane = threadIdx.x & 31;
    const int w    = threadIdx.x >> 5;
    const int b    = blockIdx.z;
    const int hh   = blockIdx.y;
    const int qrow = blockIdx.x * 8 + w;

    __shared__ float Ks[32][33];
    __shared__ float Vs[32][33];
    __shared__ int   Ms[32];

    const float* qp = q + (size_t)(b * SEQ + qrow) * DIM + hh * HSZ;
    float qreg[32];
    #pragma unroll
    for (int d = 0; d < 32; d++) qreg[d] = qp[d];

    float m = -INFINITY, l = 0.f, acc = 0.f;
    const float scale = 0.17677669529663687f;  // 1/sqrt(32)

    for (int kt = 0; kt < SEQ / 32; kt++) {
        __syncthreads();
        for (int i = threadIdx.x; i < 32 * 32; i += 256) {
            const int r = i >> 5, c = i & 31;
            const size_t g = (size_t)(b * SEQ + kt * 32 + r) * DIM + hh * HSZ + c;
            Ks[r][c] = k[g];
            Vs[r][c] = v[g];
        }
        if (threadIdx.x < 32) Ms[threadIdx.x] = mask[b * SEQ + kt * 32 + threadIdx.x];
        __syncthreads();

        float sc = 0.f;
        #pragma unroll
        for (int d = 0; d < 32; d++) sc = fmaf(qreg[d], Ks[lane][d], sc);
        sc *= scale;
        if (Ms[lane] == 0) sc += -1e30f;

        float tm = sc;
        #pragma unroll
        for (int o = 16; o > 0; o >>= 1) tm = fmaxf(tm, __shfl_xor_sync(0xffffffffu, tm, o));
        const float mn   = fmaxf(m, tm);
        const float corr = __expf(m - mn);
        const float p    = __expf(sc - mn);
        float ps = p;
        #pragma unroll
        for (int o = 16; o > 0; o >>= 1) ps += __shfl_xor_sync(0xffffffffu, ps, o);
        l   = l * corr + ps;
        acc *= corr;
        #pragma unroll
        for (int j = 0; j < 32; j++) {
            const float pj = __shfl_sync(0xffffffffu, p, j);
            acc = fmaf(pj, Vs[j][lane], acc);
        }
        m = mn;
    }

    out[(size_t)(b * SEQ + qrow) * DIM + hh * HSZ + lane] = acc / l;
}

// ---------------- launch ----------------
extern "C" void kernel_launch(void* const* d_in, const int* in_sizes, int n_in,
                              void* d_out, int out_size)
{
    const float* x    = (const float*)d_in[0];
    const float* ln1g = (const float*)d_in[1];
    const float* ln1b = (const float*)d_in[2];
    const float* Wq   = (const float*)d_in[3];
    const float* bq   = (const float*)d_in[4];
    const float* Wk   = (const float*)d_in[5];
    const float* bk   = (const float*)d_in[6];
    const float* Wv   = (const float*)d_in[7];
    const float* bv   = (const float*)d_in[8];
    const float* ln2g = (const float*)d_in[9];
    const float* ln2b = (const float*)d_in[10];
    const float* Wo1  = (const float*)d_in[11];
    const float* bo1  = (const float*)d_in[12];
    const float* Wo2  = (const float*)d_in[13];
    const float* bo2  = (const float*)d_in[14];
    const int*   mask = (const int*)d_in[15];
    float* out = (float*)d_out;

    float *h, *t, *q, *k, *v, *attn, *res, *o1;
    cudaGetSymbolAddress((void**)&h,    g_h);
    cudaGetSymbolAddress((void**)&t,    g_t);
    cudaGetSymbolAddress((void**)&q,    g_q);
    cudaGetSymbolAddress((void**)&k,    g_k);
    cudaGetSymbolAddress((void**)&v,    g_v);
    cudaGetSymbolAddress((void**)&attn, g_attn);
    cudaGetSymbolAddress((void**)&res,  g_res);
    cudaGetSymbolAddress((void**)&o1,   g_o1);

    const dim3 gG(DIM / 64, NTOK / 64);  // (4, 128)
    const int  LOFF = 3 * DIM * DIM;     // layer stride in W[L,K,D,D]

    // h = LN1(x)
    ln_kernel<<<NTOK, 256>>>(x, nullptr, ln1g, ln1b, nullptr, h);

    // q/k/v = temporal_encoder(h): conv3(gelu) -> conv3
    gemm_kernel<true, 1><<<gG, 256>>>(h, Wq,        bq,       nullptr, t, 3 * DIM);
    gemm_kernel<true, 0><<<gG, 256>>>(t, Wq + LOFF, bq + DIM, nullptr, q, 3 * DIM);
    gemm_kernel<true, 1><<<gG, 256>>>(h, Wk,        bk,       nullptr, t, 3 * DIM);
    gemm_kernel<true, 0><<<gG, 256>>>(t, Wk + LOFF, bk + DIM, nullptr, k, 3 * DIM);
    gemm_kernel<true, 1><<<gG, 256>>>(h, Wv,        bv,       nullptr, t, 3 * DIM);
    gemm_kernel<true, 0><<<gG, 256>>>(t, Wv + LOFF, bv + DIM, nullptr, v, 3 * DIM);

    // masked softmax attention (flash, no score materialization)
    attn_kernel<<<dim3(SEQ / 8, NH, BATCH), 256>>>(q, k, v, mask, attn);

    // res = x + attn ; o1 = LN2(res)
    ln_kernel<<<NTOK, 256>>>(x, attn, ln2g, ln2b, res, o1);

    // out = gelu(o1 @ Wo1 + bo1) @ Wo2 + bo2 + res
    gemm_kernel<false, 1><<<gG, 256>>>(o1, Wo1, bo1, nullptr, t,   DIM);
    gemm_kernel<false, 2><<<gG, 256>>>(t,  Wo2, bo2, res,     out, DIM);
}

// round 3
// speedup vs baseline: 3.3002x; 3.3002x over previous
#include <cuda_runtime.h>
#include <math.h>

#define BATCH 4
#define SEQ   2048
#define DIM   256
#define NH    8
#define HSZ   32
#define NTOK  (BATCH*SEQ)        /* 8192 */
#define NELEM (NTOK*DIM)         /* 2097152 */

// ---------------- scratch (allocation-free: __device__ globals) ----------------
__device__ float g_h[NELEM];
__device__ float g_t[NELEM];
__device__ float g_q[NELEM];
__device__ float g_k[NELEM];
__device__ float g_v[NELEM];
__device__ float g_attn[NELEM];
__device__ float g_res[NELEM];
__device__ float g_o1[NELEM];
__device__ int   g_idx[BATCH*SEQ];
__device__ int   g_cnt[BATCH];

// ---------------- helpers ----------------
__device__ __forceinline__ float gelu_f(float x) {
    float x3 = x * x * x;
    return 0.5f * x * (1.f + tanhf(0.7978845608028654f * (x + 0.044715f * x3)));
}

// ---------------- mask compaction (deterministic prefix scan) ----------------
// One block per batch; keys with mask==0 contribute exactly 0 to softmax
// (exp(-1e30 - max) == 0 in fp32), so attention may skip them entirely.
__global__ void compact_kernel(const int* __restrict__ mask,
                               int* __restrict__ idx, int* __restrict__ cnt)
{
    const int b = blockIdx.x;
    const int t = threadIdx.x;          // 256 threads, 8 keys each
    __shared__ int warp_tot[8];

    int mv[8]; int c = 0;
    const int s0 = t * 8;
    #pragma unroll
    for (int j = 0; j < 8; j++) { mv[j] = mask[b*SEQ + s0 + j]; c += (mv[j] != 0); }

    const int lane = t & 31, w = t >> 5;
    int sc = c;
    #pragma unroll
    for (int o = 1; o < 32; o <<= 1) {
        int n = __shfl_up_sync(0xffffffffu, sc, o);
        if (lane >= o) sc += n;
    }
    if (lane == 31) warp_tot[w] = sc;
    __syncthreads();
    int wbase = 0;
    for (int i = 0; i < w; i++) wbase += warp_tot[i];
    int pos = wbase + sc - c;           // exclusive prefix
    #pragma unroll
    for (int j = 0; j < 8; j++) if (mv[j]) idx[b*SEQ + pos++] = s0 + j;
    __syncthreads();
    if (t == 0) {
        int tot = 0;
        for (int i = 0; i < 8; i++) tot += warp_tot[i];
        cnt[b] = tot;
        const int pad = (tot + 31) & ~31;     // pad to tile multiple with idx 0
        for (int i = tot; i < pad; i++) idx[b*SEQ + i] = 0;
    }
}

// ---------------- LayerNorm (optionally fused residual add) ----------------
__global__ void ln_kernel(const float* __restrict__ x, const float* __restrict__ add,
                          const float* __restrict__ gamma, const float* __restrict__ beta,
                          float* __restrict__ res_out, float* __restrict__ out)
{
    const int t = blockIdx.x;
    const int d = threadIdx.x;
    const int idx = t * DIM + d;
    float v = x[idx];
    if (add) v += add[idx];
    if (res_out) res_out[idx] = v;

    __shared__ float sh[8];
    const int lane = d & 31, w = d >> 5;

    float s = v;
    #pragma unroll
    for (int o = 16; o > 0; o >>= 1) s += __shfl_xor_sync(0xffffffffu, s, o);
    if (lane == 0) sh[w] = s;
    __syncthreads();
    float tot = 0.f;
    #pragma unroll
    for (int i = 0; i < 8; i++) tot += sh[i];
    const float mean = tot * (1.f / 256.f);
    const float dv = v - mean;

    float s2 = dv * dv;
    #pragma unroll
    for (int o = 16; o > 0; o >>= 1) s2 += __shfl_xor_sync(0xffffffffu, s2, o);
    __syncthreads();
    if (lane == 0) sh[w] = s2;
    __syncthreads();
    float tot2 = 0.f;
    #pragma unroll
    for (int i = 0; i < 8; i++) tot2 += sh[i];
    const float var = tot2 * (1.f / 256.f);

    out[idx] = dv * rsqrtf(var + 1e-6f) * gamma[d] + beta[d];
}

// ---------------- GEMM: C[M,256] = A' @ B + bias (+epilogue) ----------------
// BM=128, BN=64, BK=16, 256 threads, 8x4 micro-tile.
// CONV=true: im2col gather of kernel-3 SAME conv (3 contiguous token rows).
// EPI: 0=none, 1=gelu, 2=+resid
template<bool CONV, int EPI>
__global__ void __launch_bounds__(256)
gemm_kernel(const float* __restrict__ A, const float* __restrict__ Bm,
            const float* __restrict__ bias, const float* __restrict__ resid,
            float* __restrict__ C, int Kdim)
{
    __shared__ float As[16][132];   // transposed: As[k][m]; stride 132 keeps LDS.128 aligned
    __shared__ float Bs[16][64];

    const int tid  = threadIdx.x;
    const int tx   = tid & 15;           // 16 col-groups of 4
    const int ty   = tid >> 4;           // 16 row-groups of 8
    const int row0 = blockIdx.y * 128;
    const int col0 = blockIdx.x * 64;

    float acc[8][4];
    #pragma unroll
    for (int i = 0; i < 8; i++)
        #pragma unroll
        for (int j = 0; j < 4; j++) acc[i][j] = 0.f;

    for (int kk0 = 0; kk0 < Kdim; kk0 += 16) {
        // A tile: 128x16 = 512 float4, 2 per thread
        #pragma unroll
        for (int u = 0; u < 2; u++) {
            const int id = tid + 256 * u;
            const int m  = row0 + (id >> 2);
            const int kg = (id & 3) << 2;        // k offset within tile (0,4,8,12)
            const int kk = kk0 + kg;
            float4 av;
            if (CONV) {
                const int s  = m & (SEQ - 1);
                const int ks = kk >> 8;          // tap 0..2 (16-chunks never cross taps)
                if ((unsigned)(s + ks - 1) < (unsigned)SEQ)
                    av = *(const float4*)&A[m * DIM + kk - DIM];
                else
                    av = make_float4(0.f, 0.f, 0.f, 0.f);
            } else {
                av = *(const float4*)&A[m * Kdim + kk];
            }
            const int mm = id >> 2;
            As[kg + 0][mm] = av.x;
            As[kg + 1][mm] = av.y;
            As[kg + 2][mm] = av.z;
            As[kg + 3][mm] = av.w;
        }
        // B tile: 16x64 = 256 float4, 1 per thread
        {
            const int r  = tid >> 4;
            const int c4 = (tid & 15) << 2;
            *(float4*)&Bs[r][c4] = *(const float4*)&Bm[(kk0 + r) * DIM + col0 + c4];
        }
        __syncthreads();

        #pragma unroll
        for (int k = 0; k < 16; k++) {
            const float4 a0 = *(const float4*)&As[k][ty * 8];
            const float4 a1 = *(const float4*)&As[k][ty * 8 + 4];
            const float4 b4 = *(const float4*)&Bs[k][tx * 4];
            const float a[8] = {a0.x, a0.y, a0.z, a0.w, a1.x, a1.y, a1.z, a1.w};
            const float b[4] = {b4.x, b4.y, b4.z, b4.w};
            #pragma unroll
            for (int i = 0; i < 8; i++)
                #pragma unroll
                for (int j = 0; j < 4; j++) acc[i][j] = fmaf(a[i], b[j], acc[i][j]);
        }
        __syncthreads();
    }

    #pragma unroll
    for (int i = 0; i < 8; i++) {
        const int row = row0 + ty * 8 + i;
        #pragma unroll
        for (int j = 0; j < 4; j++) {
            const int col = col0 + tx * 4 + j;
            float c = acc[i][j] + bias[col];
            if (EPI == 1) c = gelu_f(c);
            if (EPI == 2) c += resid[row * DIM + col];
            C[row * DIM + col] = c;
        }
    }
}

// ---------------- Flash attention over compacted keys ----------------
// grid = (SEQ/64, NH, BATCH), block = 128. Br=64 queries, Bc=32 keys.
// Thread owns a 4x4 tile: rows r0..r0+3 of S/O, cols c0..c0+3 (keys) / dims d0..d0+3.
__global__ void __launch_bounds__(128)
attn_kernel(const float* __restrict__ q, const float* __restrict__ k,
            const float* __restrict__ v, const int* __restrict__ idx,
            const int* __restrict__ cntp, float* __restrict__ out)
{
    __shared__ float Qs[32][68];   // [dim][qrow], stride 68 -> 16B-aligned float4 rows
    __shared__ float Ks[32][36];   // [dim][key]
    __shared__ float Vs[32][36];   // [key][dim]
    __shared__ float Ps[32][68];   // [key][qrow]

    const int b   = blockIdx.z;
    const int hh  = blockIdx.y;
    const int q0  = blockIdx.x * 64;
    const int tid = threadIdx.x;
    const int cg  = tid & 7;       // col-group (keys / dims)
    const int rg  = tid >> 3;      // row-group (16 groups x 4 rows)
    const int r0  = rg * 4;
    const int c0  = cg * 4;

    const float scale = 0.17677669529663687f;   // 1/sqrt(32)

    // load Q tile, pre-scaled
    for (int i = tid; i < 64 * 32; i += 128) {
        const int r = i >> 5, d = i & 31;
        Qs[d][r] = q[(size_t)(b * SEQ + q0 + r) * DIM + hh * HSZ + d] * scale;
    }

    const int cnt = cntp[b];
    const int nt  = (cnt + 31) >> 5;

    float m4[4], l4[4], acc[4][4];
    #pragma unroll
    for (int i = 0; i < 4; i++) {
        m4[i] = -INFINITY; l4[i] = 0.f;
        #pragma unroll
        for (int j = 0; j < 4; j++) acc[i][j] = 0.f;
    }

    for (int kt = 0; kt < nt; kt++) {
        __syncthreads();
        // gather K/V tile (32 unmasked keys); each K/V row is one 128B segment
        for (int i = tid; i < 32 * 32; i += 128) {
            const int rr = i >> 5, d = i & 31;
            const int src = idx[b * SEQ + kt * 32 + rr];
            const size_t g = (size_t)(b * SEQ + src) * DIM + hh * HSZ + d;
            Ks[d][rr] = k[g];
            Vs[rr][d] = v[g];
        }
        __syncthreads();

        // S = Q K^T (outer product over dims)
        float s[4][4];
        #pragma unroll
        for (int i = 0; i < 4; i++)
            #pragma unroll
            for (int j = 0; j < 4; j++) s[i][j] = 0.f;
        #pragma unroll
        for (int d = 0; d < 32; d++) {
            const float4 qa = *(const float4*)&Qs[d][r0];
            const float4 kb = *(const float4*)&Ks[d][c0];
            const float a[4] = {qa.x, qa.y, qa.z, qa.w};
            const float bb[4] = {kb.x, kb.y, kb.z, kb.w};
            #pragma unroll
            for (int i = 0; i < 4; i++)
                #pragma unroll
                for (int j = 0; j < 4; j++) s[i][j] = fmaf(a[i], bb[j], s[i][j]);
        }
        // invalidate padded columns in the last tile
        if (kt == nt - 1) {
            #pragma unroll
            for (int j = 0; j < 4; j++)
                if (kt * 32 + c0 + j >= cnt) {
                    #pragma unroll
                    for (int i = 0; i < 4; i++) s[i][j] = -1e30f;
                }
        }

        // online softmax, rows split across the 8 threads of a col-group row
        float p[4][4];
        #pragma unroll
        for (int i = 0; i < 4; i++) {
            float tm = fmaxf(fmaxf(s[i][0], s[i][1]), fmaxf(s[i][2], s[i][3]));
            tm = fmaxf(tm, __shfl_xor_sync(0xffffffffu, tm, 1));
            tm = fmaxf(tm, __shfl_xor_sync(0xffffffffu, tm, 2));
            tm = fmaxf(tm, __shfl_xor_sync(0xffffffffu, tm, 4));
            const float mn   = fmaxf(m4[i], tm);
            const float corr = __expf(m4[i] - mn);
            m4[i] = mn;
            float ps = 0.f;
            #pragma unroll
            for (int j = 0; j < 4; j++) { p[i][j] = __expf(s[i][j] - mn); ps += p[i][j]; }
            ps += __shfl_xor_sync(0xffffffffu, ps, 1);
            ps += __shfl_xor_sync(0xffffffffu, ps, 2);
            ps += __shfl_xor_sync(0xffffffffu, ps, 4);
            l4[i] = l4[i] * corr + ps;
            #pragma unroll
            for (int j = 0; j < 4; j++) acc[i][j] *= corr;
        }

        // P through smem, then O += P V (outer product over keys)
        #pragma unroll
        for (int i = 0; i < 4; i++)
            #pragma unroll
            for (int j = 0; j < 4; j++) Ps[c0 + j][r0 + i] = p[i][j];
        __syncthreads();
        #pragma unroll
        for (int c = 0; c < 32; c++) {
            const float4 pa = *(const float4*)&Ps[c][r0];
            const float4 vb = *(const float4*)&Vs[c][c0];
            const float pr[4] = {pa.x, pa.y, pa.z, pa.w};
            const float vv[4] = {vb.x, vb.y, vb.z, vb.w};
            #pragma unroll
            for (int i = 0; i < 4; i++)
                #pragma unroll
                for (int j = 0; j < 4; j++) acc[i][j] = fmaf(pr[i], vv[j], acc[i][j]);
        }
    }

    #pragma unroll
    for (int i = 0; i < 4; i++) {
        const float inv = 1.f / l4[i];
        float4 o4 = make_float4(acc[i][0] * inv, acc[i][1] * inv,
                                acc[i][2] * inv, acc[i][3] * inv);
        *(float4*)&out[(size_t)(b * SEQ + q0 + r0 + i) * DIM + hh * HSZ + c0] = o4;
    }
}

// ---------------- launch ----------------
extern "C" void kernel_launch(void* const* d_in, const int* in_sizes, int n_in,
                              void* d_out, int out_size)
{
    const float* x    = (const float*)d_in[0];
    const float* ln1g = (const float*)d_in[1];
    const float* ln1b = (const float*)d_in[2];
    const float* Wq   = (const float*)d_in[3];
    const float* bq   = (const float*)d_in[4];
    const float* Wk   = (const float*)d_in[5];
    const float* bk   = (const float*)d_in[6];
    const float* Wv   = (const float*)d_in[7];
    const float* bv   = (const float*)d_in[8];
    const float* ln2g = (const float*)d_in[9];
    const float* ln2b = (const float*)d_in[10];
    const float* Wo1  = (const float*)d_in[11];
    const float* bo1  = (const float*)d_in[12];
    const float* Wo2  = (const float*)d_in[13];
    const float* bo2  = (const float*)d_in[14];
    const int*   mask = (const int*)d_in[15];
    float* out = (float*)d_out;

    float *h, *t, *q, *k, *v, *attn, *res, *o1;
    int *idx, *cnt;
    cudaGetSymbolAddress((void**)&h,    g_h);
    cudaGetSymbolAddress((void**)&t,    g_t);
    cudaGetSymbolAddress((void**)&q,    g_q);
    cudaGetSymbolAddress((void**)&k,    g_k);
    cudaGetSymbolAddress((void**)&v,    g_v);
    cudaGetSymbolAddress((void**)&attn, g_attn);
    cudaGetSymbolAddress((void**)&res,  g_res);
    cudaGetSymbolAddress((void**)&o1,   g_o1);
    cudaGetSymbolAddress((void**)&idx,  g_idx);
    cudaGetSymbolAddress((void**)&cnt,  g_cnt);

    const dim3 gG(DIM / 64, NTOK / 128);  // (4, 64)
    const int  LOFF = 3 * DIM * DIM;      // layer stride in W[L,K,D,D]

    compact_kernel<<<BATCH, 256>>>(mask, idx, cnt);

    // h = LN1(x)
    ln_kernel<<<NTOK, 256>>>(x, nullptr, ln1g, ln1b, nullptr, h);

    // q/k/v = temporal_encoder(h): conv3+gelu -> conv3
    gemm_kernel<true, 1><<<gG, 256>>>(h, Wq,        bq,       nullptr, t, 3 * DIM);
    gemm_kernel<true, 0><<<gG, 256>>>(t, Wq + LOFF, bq + DIM, nullptr, q, 3 * DIM);
    gemm_kernel<true, 1><<<gG, 256>>>(h, Wk,        bk,       nullptr, t, 3 * DIM);
    gemm_kernel<true, 0><<<gG, 256>>>(t, Wk + LOFF, bk + DIM, nullptr, k, 3 * DIM);
    gemm_kernel<true, 1><<<gG, 256>>>(h, Wv,        bv,       nullptr, t, 3 * DIM);
    gemm_kernel<true, 0><<<gG, 256>>>(t, Wv + LOFF, bv + DIM, nullptr, v, 3 * DIM);

    // masked softmax attention over compacted (unmasked) keys only
    attn_kernel<<<dim3(SEQ / 64, NH, BATCH), 128>>>(q, k, v, idx, cnt, attn);

    // res = x + attn ; o1 = LN2(res)
    ln_kernel<<<NTOK, 256>>>(x, attn, ln2g, ln2b, res, o1);

    // out = gelu(o1 @ Wo1 + bo1) @ Wo2 + bo2 + res
    gemm_kernel<false, 1><<<gG, 256>>>(o1, Wo1, bo1, nullptr, t,   DIM);
    gemm_kernel<false, 2><<<gG, 256>>>(t,  Wo2, bo2, res,     out, DIM);
}

// round 10
// speedup vs baseline: 3.6361x; 1.1018x over previous
#include <cuda_runtime.h>
#include <math.h>

#define BATCH 4
#define SEQ   2048
#define DIM   256
#define NH    8
#define HSZ   32
#define NTOK  (BATCH*SEQ)        /* 8192 */
#define NELEM (NTOK*DIM)         /* 2097152 */

// ---------------- scratch (allocation-free: __device__ globals) ----------------
__device__ float g_h[NELEM];
__device__ float g_t3[NTOK*768];     // fused layer-1 output [8192][768] (q|k|v)
__device__ float g_q[NELEM];
__device__ float g_k[NELEM];
__device__ float g_v[NELEM];
__device__ float g_attn[NELEM];
__device__ float g_res[NELEM];
__device__ float g_o1[NELEM];
__device__ float g_wcat[768*768];    // concat layer-1 weights [k=768][n=768]
__device__ float g_bcat[768];
__device__ int   g_idx[BATCH*SEQ];
__device__ int   g_cnt[BATCH];

// ---------------- helpers ----------------
__device__ __forceinline__ float gelu_f(float x) {
    float x3 = x * x * x;
    return 0.5f * x * (1.f + tanhf(0.7978845608028654f * (x + 0.044715f * x3)));
}

// ---------------- prep: concat layer-1 weights/bias along N ----------------
__global__ void wcat_kernel(const float* __restrict__ Wq, const float* __restrict__ Wk,
                            const float* __restrict__ Wv, const float* __restrict__ bq,
                            const float* __restrict__ bk, const float* __restrict__ bv,
                            float* __restrict__ wcat, float* __restrict__ bcat)
{
    const int i = blockIdx.x * 256 + threadIdx.x;   // 768*768 elements
    if (i >= 768 * 768) return;
    const int kk = i / 768;
    const int n  = i - kk * 768;
    const int sel = n >> 8, nn = n & 255;
    const float* W = sel == 0 ? Wq : (sel == 1 ? Wk : Wv);
    wcat[i] = W[kk * 256 + nn];                      // layer0: [kk=ks*256+in][out]
    if (i < 768) {
        const float* bb = sel == 0 ? bq : (sel == 1 ? bk : bv);
        bcat[i] = bb[nn];
    }
}

// ---------------- mask compaction (deterministic prefix scan) ----------------
__global__ void compact_kernel(const int* __restrict__ mask,
                               int* __restrict__ idx, int* __restrict__ cnt)
{
    const int b = blockIdx.x;
    const int t = threadIdx.x;          // 256 threads, 8 keys each
    __shared__ int warp_tot[8];

    int mv[8]; int c = 0;
    const int s0 = t * 8;
    #pragma unroll
    for (int j = 0; j < 8; j++) { mv[j] = mask[b*SEQ + s0 + j]; c += (mv[j] != 0); }

    const int lane = t & 31, w = t >> 5;
    int sc = c;
    #pragma unroll
    for (int o = 1; o < 32; o <<= 1) {
        int n = __shfl_up_sync(0xffffffffu, sc, o);
        if (lane >= o) sc += n;
    }
    if (lane == 31) warp_tot[w] = sc;
    __syncthreads();
    int wbase = 0;
    for (int i = 0; i < w; i++) wbase += warp_tot[i];
    int pos = wbase + sc - c;           // exclusive prefix
    #pragma unroll
    for (int j = 0; j < 8; j++) if (mv[j]) idx[b*SEQ + pos++] = s0 + j;
    __syncthreads();
    if (t == 0) {
        int tot = 0;
        for (int i = 0; i < 8; i++) tot += warp_tot[i];
        cnt[b] = tot;
        const int pad = (tot + 31) & ~31;
        for (int i = tot; i < pad; i++) idx[b*SEQ + i] = 0;
    }
}

// ---------------- LayerNorm (optionally fused residual add) ----------------
__global__ void ln_kernel(const float* __restrict__ x, const float* __restrict__ add,
                          const float* __restrict__ gamma, const float* __restrict__ beta,
                          float* __restrict__ res_out, float* __restrict__ out)
{
    const int t = blockIdx.x;
    const int d = threadIdx.x;
    const int idx = t * DIM + d;
    float v = x[idx];
    if (add) v += add[idx];
    if (res_out) res_out[idx] = v;

    __shared__ float sh[8];
    const int lane = d & 31, w = d >> 5;

    float s = v;
    #pragma unroll
    for (int o = 16; o > 0; o >>= 1) s += __shfl_xor_sync(0xffffffffu, s, o);
    if (lane == 0) sh[w] = s;
    __syncthreads();
    float tot = 0.f;
    #pragma unroll
    for (int i = 0; i < 8; i++) tot += sh[i];
    const float mean = tot * (1.f / 256.f);
    const float dv = v - mean;

    float s2 = dv * dv;
    #pragma unroll
    for (int o = 16; o > 0; o >>= 1) s2 += __shfl_xor_sync(0xffffffffu, s2, o);
    __syncthreads();
    if (lane == 0) sh[w] = s2;
    __syncthreads();
    float tot2 = 0.f;
    #pragma unroll
    for (int i = 0; i < 8; i++) tot2 += sh[i];
    const float var = tot2 * (1.f / 256.f);

    out[idx] = dv * rsqrtf(var + 1e-6f) * gamma[d] + beta[d];
}

// ---------------- GEMM: C[M, N] = A' @ B + bias (+epilogue) ----------------
// BM=64, BN=64, BK=16, 128 threads, 8x4 micro-tile, double-buffered smem.
// CONV: im2col gather of kernel-3 SAME conv (3 contiguous token rows; a BK=16
//       chunk never crosses a tap boundary, so the tap index is tile-uniform).
// B3:   blockIdx.z selects one of 3 (B, bias, C) sets and A column offset z*256.
// EPI:  0=none, 1=gelu, 2=+resid
template<bool CONV, int EPI, bool B3>
__global__ void __launch_bounds__(128)
gemm_kernel(const float* __restrict__ A, int lda,
            const float* __restrict__ B0, const float* __restrict__ B1,
            const float* __restrict__ B2, int ldb,
            const float* __restrict__ bi0, const float* __restrict__ bi1,
            const float* __restrict__ bi2,
            const float* __restrict__ resid,
            float* __restrict__ C0, float* __restrict__ C1, float* __restrict__ C2,
            int ldc, int Kdim)
{
    const float* Bm; const float* bias; float* C; int acol;
    if (B3) {
        const int z = blockIdx.z;
        Bm   = z == 0 ? B0  : (z == 1 ? B1  : B2);
        bias = z == 0 ? bi0 : (z == 1 ? bi1 : bi2);
        C    = z == 0 ? C0  : (z == 1 ? C1  : C2);
        acol = z << 8;
    } else { Bm = B0; bias = bi0; C = C0; acol = 0; }

    __shared__ float As[2][16][68];
    __shared__ float Bs[2][16][68];

    const int tid  = threadIdx.x;
    const int tx   = tid & 15;          // 16 col-groups of 4
    const int ty   = tid >> 4;          // 8 row-groups of 8
    const int row0 = blockIdx.y * 64;
    const int col0 = blockIdx.x * 64;

    // loader geometry: A tile 64x16 (2 float4/thread), B tile 16x64 (2 float4/thread)
    const int rowA = tid >> 2;          // 0..31 (and +32)
    const int kgA  = (tid & 3) << 2;    // 0,4,8,12
    const int rB   = tid >> 4;          // 0..7 (and +8)
    const int cB   = (tid & 15) << 2;

    float4 aR0, aR1, bR0, bR1;
    const float4 z4 = make_float4(0.f, 0.f, 0.f, 0.f);

    auto ldg = [&](int kk0) {
        if (CONV) {
            const int ks   = kk0 >> 8;            // tile-uniform tap
            const int base = kk0 - (ks << 8);
            const int m0 = row0 + rowA;
            const int s0 = m0 & (SEQ - 1);
            aR0 = ((unsigned)(s0 + ks - 1) < (unsigned)SEQ)
                ? *(const float4*)&A[(size_t)(m0 + ks - 1) * lda + acol + base + kgA] : z4;
            const int m1 = m0 + 32;
            const int s1 = m1 & (SEQ - 1);
            aR1 = ((unsigned)(s1 + ks - 1) < (unsigned)SEQ)
                ? *(const float4*)&A[(size_t)(m1 + ks - 1) * lda + acol + base + kgA] : z4;
        } else {
            aR0 = *(const float4*)&A[(size_t)(row0 + rowA)      * lda + kk0 + kgA];
            aR1 = *(const float4*)&A[(size_t)(row0 + rowA + 32) * lda + kk0 + kgA];
        }
        bR0 = *(const float4*)&Bm[(size_t)(kk0 + rB)     * ldb + col0 + cB];
        bR1 = *(const float4*)&Bm[(size_t)(kk0 + rB + 8) * ldb + col0 + cB];
    };
    auto sts = [&](int buf) {
        As[buf][kgA + 0][rowA] = aR0.x;  As[buf][kgA + 1][rowA] = aR0.y;
        As[buf][kgA + 2][rowA] = aR0.z;  As[buf][kgA + 3][rowA] = aR0.w;
        As[buf][kgA + 0][rowA + 32] = aR1.x;  As[buf][kgA + 1][rowA + 32] = aR1.y;
        As[buf][kgA + 2][rowA + 32] = aR1.z;  As[buf][kgA + 3][rowA + 32] = aR1.w;
        *(float4*)&Bs[buf][rB][cB]     = bR0;
        *(float4*)&Bs[buf][rB + 8][cB] = bR1;
    };

    float acc[8][4];
    #pragma unroll
    for (int i = 0; i < 8; i++)
        #pragma unroll
        for (int j = 0; j < 4; j++) acc[i][j] = 0.f;

    ldg(0); sts(0); __syncthreads();
    const int NIT = Kdim >> 4;
    for (int it = 0; it < NIT; ++it) {
        const int cur = it & 1;
        if (it + 1 < NIT) ldg((it + 1) << 4);
        #pragma unroll
        for (int k = 0; k < 16; k++) {
            const float4 a0 = *(const float4*)&As[cur][k][ty * 8];
            const float4 a1 = *(const float4*)&As[cur][k][ty * 8 + 4];
            const float4 b4 = *(const float4*)&Bs[cur][k][tx * 4];
            const float a[8] = {a0.x, a0.y, a0.z, a0.w, a1.x, a1.y, a1.z, a1.w};
            const float b[4] = {b4.x, b4.y, b4.z, b4.w};
            #pragma unroll
            for (int i = 0; i < 8; i++)
                #pragma unroll
                for (int j = 0; j < 4; j++) acc[i][j] = fmaf(a[i], b[j], acc[i][j]);
        }
        if (it + 1 < NIT) sts(1 - cur);
        __syncthreads();
    }

    #pragma unroll
    for (int i = 0; i < 8; i++) {
        const int row = row0 + ty * 8 + i;
        #pragma unroll
        for (int j = 0; j < 4; j++) {
            const int col = col0 + tx * 4 + j;
            float c = acc[i][j] + bias[col];
            if (EPI == 1) c = gelu_f(c);
            if (EPI == 2) c += resid[row * ldc + col];
            C[(size_t)row * ldc + col] = c;
        }
    }
}

// ---------------- Flash attention over compacted keys ----------------
// grid = (SEQ/64, NH, BATCH), block = 128. Br=64 queries, Bc=32 keys.
__global__ void __launch_bounds__(128)
attn_kernel(const float* __restrict__ q, const float* __restrict__ k,
            const float* __restrict__ v, const int* __restrict__ idx,
            const int* __restrict__ cntp, float* __restrict__ out)
{
    __shared__ float Qs[32][68];
    __shared__ float Ks[32][36];
    __shared__ float Vs[32][36];
    __shared__ float Ps[32][68];

    const int b   = blockIdx.z;
    const int hh  = blockIdx.y;
    const int q0  = blockIdx.x * 64;
    const int tid = threadIdx.x;
    const int cg  = tid & 7;
    const int rg  = tid >> 3;
    const int r0  = rg * 4;
    const int c0  = cg * 4;

    const float scale = 0.17677669529663687f;   // 1/sqrt(32)

    for (int i = tid; i < 64 * 32; i += 128) {
        const int r = i >> 5, d = i & 31;
        Qs[d][r] = q[(size_t)(b * SEQ + q0 + r) * DIM + hh * HSZ + d] * scale;
    }

    const int cnt = cntp[b];
    const int nt  = (cnt + 31) >> 5;

    float m4[4], l4[4], acc[4][4];
    #pragma unroll
    for (int i = 0; i < 4; i++) {
        m4[i] = -INFINITY; l4[i] = 0.f;
        #pragma unroll
        for (int j = 0; j < 4; j++) acc[i][j] = 0.f;
    }

    for (int kt = 0; kt < nt; kt++) {
        __syncthreads();
        for (int i = tid; i < 32 * 32; i += 128) {
            const int rr = i >> 5, d = i & 31;
            const int src = idx[b * SEQ + kt * 32 + rr];
            const size_t g = (size_t)(b * SEQ + src) * DIM + hh * HSZ + d;
            Ks[d][rr] = k[g];
            Vs[rr][d] = v[g];
        }
        __syncthreads();

        float s[4][4];
        #pragma unroll
        for (int i = 0; i < 4; i++)
            #pragma unroll
            for (int j = 0; j < 4; j++) s[i][j] = 0.f;
        #pragma unroll
        for (int d = 0; d < 32; d++) {
            const float4 qa = *(const float4*)&Qs[d][r0];
            const float4 kb = *(const float4*)&Ks[d][c0];
            const float a[4] = {qa.x, qa.y, qa.z, qa.w};
            const float bb[4] = {kb.x, kb.y, kb.z, kb.w};
            #pragma unroll
            for (int i = 0; i < 4; i++)
                #pragma unroll
                for (int j = 0; j < 4; j++) s[i][j] = fmaf(a[i], bb[j], s[i][j]);
        }
        if (kt == nt - 1) {
            #pragma unroll
            for (int j = 0; j < 4; j++)
                if (kt * 32 + c0 + j >= cnt) {
                    #pragma unroll
                    for (int i = 0; i < 4; i++) s[i][j] = -1e30f;
                }
        }

        float p[4][4];
        #pragma unroll
        for (int i = 0; i < 4; i++) {
            float tm = fmaxf(fmaxf(s[i][0], s[i][1]), fmaxf(s[i][2], s[i][3]));
            tm = fmaxf(tm, __shfl_xor_sync(0xffffffffu, tm, 1));
            tm = fmaxf(tm, __shfl_xor_sync(0xffffffffu, tm, 2));
            tm = fmaxf(tm, __shfl_xor_sync(0xffffffffu, tm, 4));
            const float mn   = fmaxf(m4[i], tm);
            const float corr = __expf(m4[i] - mn);
            m4[i] = mn;
            float ps = 0.f;
            #pragma unroll
            for (int j = 0; j < 4; j++) { p[i][j] = __expf(s[i][j] - mn); ps += p[i][j]; }
            ps += __shfl_xor_sync(0xffffffffu, ps, 1);
            ps += __shfl_xor_sync(0xffffffffu, ps, 2);
            ps += __shfl_xor_sync(0xffffffffu, ps, 4);
            l4[i] = l4[i] * corr + ps;
            #pragma unroll
            for (int j = 0; j < 4; j++) acc[i][j] *= corr;
        }

        #pragma unroll
        for (int i = 0; i < 4; i++)
            #pragma unroll
            for (int j = 0; j < 4; j++) Ps[c0 + j][r0 + i] = p[i][j];
        __syncthreads();
        #pragma unroll
        for (int c = 0; c < 32; c++) {
            const float4 pa = *(const float4*)&Ps[c][r0];
            const float4 vb = *(const float4*)&Vs[c][c0];
            const float pr[4] = {pa.x, pa.y, pa.z, pa.w};
            const float vv[4] = {vb.x, vb.y, vb.z, vb.w};
            #pragma unroll
            for (int i = 0; i < 4; i++)
                #pragma unroll
                for (int j = 0; j < 4; j++) acc[i][j] = fmaf(pr[i], vv[j], acc[i][j]);
        }
    }

    #pragma unroll
    for (int i = 0; i < 4; i++) {
        const float inv = 1.f / l4[i];
        float4 o4 = make_float4(acc[i][0] * inv, acc[i][1] * inv,
                                acc[i][2] * inv, acc[i][3] * inv);
        *(float4*)&out[(size_t)(b * SEQ + q0 + r0 + i) * DIM + hh * HSZ + c0] = o4;
    }
}

// ---------------- launch ----------------
extern "C" void kernel_launch(void* const* d_in, const int* in_sizes, int n_in,
                              void* d_out, int out_size)
{
    const float* x    = (const float*)d_in[0];
    const float* ln1g = (const float*)d_in[1];
    const float* ln1b = (const float*)d_in[2];
    const float* Wq   = (const float*)d_in[3];
    const float* bq   = (const float*)d_in[4];
    const float* Wk   = (const float*)d_in[5];
    const float* bk   = (const float*)d_in[6];
    const float* Wv   = (const float*)d_in[7];
    const float* bv   = (const float*)d_in[8];
    const float* ln2g = (const float*)d_in[9];
    const float* ln2b = (const float*)d_in[10];
    const float* Wo1  = (const float*)d_in[11];
    const float* bo1  = (const float*)d_in[12];
    const float* Wo2  = (const float*)d_in[13];
    const float* bo2  = (const float*)d_in[14];
    const int*   mask = (const int*)d_in[15];
    float* out = (float*)d_out;

    float *h, *t3, *q, *k, *v, *attn, *res, *o1, *wcat, *bcat;
    int *idx, *cnt;
    cudaGetSymbolAddress((void**)&h,    g_h);
    cudaGetSymbolAddress((void**)&t3,   g_t3);
    cudaGetSymbolAddress((void**)&q,    g_q);
    cudaGetSymbolAddress((void**)&k,    g_k);
    cudaGetSymbolAddress((void**)&v,    g_v);
    cudaGetSymbolAddress((void**)&attn, g_attn);
    cudaGetSymbolAddress((void**)&res,  g_res);
    cudaGetSymbolAddress((void**)&o1,   g_o1);
    cudaGetSymbolAddress((void**)&wcat, g_wcat);
    cudaGetSymbolAddress((void**)&bcat, g_bcat);
    cudaGetSymbolAddress((void**)&idx,  g_idx);
    cudaGetSymbolAddress((void**)&cnt,  g_cnt);

    const int LOFF = 3 * DIM * DIM;   // layer stride in W[L,K,D,D]

    compact_kernel<<<BATCH, 256>>>(mask, idx, cnt);
    wcat_kernel<<<(768*768 + 255)/256, 256>>>(Wq, Wk, Wv, bq, bk, bv, wcat, bcat);

    // h = LN1(x)
    ln_kernel<<<NTOK, 256>>>(x, nullptr, ln1g, ln1b, nullptr, h);

    // layer-1 convs fused along N: t3[8192,768] = gelu(conv3(h) @ Wcat + bcat)
    gemm_kernel<true, 1, false><<<dim3(12, 128), 128>>>(
        h, DIM, wcat, nullptr, nullptr, 768, bcat, nullptr, nullptr,
        nullptr, t3, nullptr, nullptr, 768, 768);

    // layer-2 convs batched over z (q,k,v)
    gemm_kernel<true, 0, true><<<dim3(4, 128, 3), 128>>>(
        t3, 768, Wq + LOFF, Wk + LOFF, Wv + LOFF, DIM,
        bq + DIM, bk + DIM, bv + DIM,
        nullptr, q, k, v, DIM, 768);

    // masked softmax attention over compacted (unmasked) keys only
    attn_kernel<<<dim3(SEQ / 64, NH, BATCH), 128>>>(q, k, v, idx, cnt, attn);

    // res = x + attn ; o1 = LN2(res)
    ln_kernel<<<NTOK, 256>>>(x, attn, ln2g, ln2b, res, o1);

    // out = gelu(o1 @ Wo1 + bo1) @ Wo2 + bo2 + res   (t3 reused as MLP scratch)
    gemm_kernel<false, 1, false><<<dim3(4, 128), 128>>>(
        o1, DIM, Wo1, nullptr, nullptr, DIM, bo1, nullptr, nullptr,
        nullptr, t3, nullptr, nullptr, DIM, DIM);
    gemm_kernel<false, 2, false><<<dim3(4, 128), 128>>>(
        t3, DIM, Wo2, nullptr, nullptr, DIM, bo2, nullptr, nullptr,
        res, out, nullptr, nullptr, DIM, DIM);
}